// round 6
// baseline (speedup 1.0000x reference)
#include <cuda_runtime.h>
#include <cuda_bf16.h>
#include <cstdint>
#include <cfloat>

#define S_LEN 2048
#define D_DIM 128
#define QPB   128
#define NKT   16
#define KTOP  32
#define RSTRIDE 272        // bf16 tile row stride (17*16B): conflict-free ldmatrix

// 512 MB global scratch for the full score matrix [BH=32][2048][2048] fp32
__device__ float g_scores[(size_t)32 * S_LEN * S_LEN];

__device__ __forceinline__ uint32_t smem_u32(const void* p) {
    uint32_t a;
    asm("{ .reg .u64 t; cvta.to.shared.u64 t, %1; cvt.u32.u64 %0, t; }" : "=r"(a) : "l"(p));
    return a;
}

__device__ __forceinline__ void ldsm4(uint32_t& r0, uint32_t& r1, uint32_t& r2, uint32_t& r3,
                                      uint32_t addr) {
    asm volatile("ldmatrix.sync.aligned.m8n8.x4.shared.b16 {%0,%1,%2,%3}, [%4];"
                 : "=r"(r0), "=r"(r1), "=r"(r2), "=r"(r3) : "r"(addr));
}

__device__ __forceinline__ void mma16816(float* c, const uint32_t* a, uint32_t b0, uint32_t b1) {
    asm volatile(
        "mma.sync.aligned.m16n8k16.row.col.f32.bf16.bf16.f32 "
        "{%0,%1,%2,%3}, {%4,%5,%6,%7}, {%8,%9}, {%0,%1,%2,%3};"
        : "+f"(c[0]), "+f"(c[1]), "+f"(c[2]), "+f"(c[3])
        : "r"(a[0]), "r"(a[1]), "r"(a[2]), "r"(a[3]), "r"(b0), "r"(b1));
}

__device__ __forceinline__ void cvt_store(char* smem, uint32_t hi_off, uint32_t lo_off,
                                          int row, int lane, float4 v) {
    __nv_bfloat16 h0 = __float2bfloat16(v.x), h1 = __float2bfloat16(v.y);
    __nv_bfloat16 h2 = __float2bfloat16(v.z), h3 = __float2bfloat16(v.w);
    __nv_bfloat16 l0 = __float2bfloat16(v.x - __bfloat162float(h0));
    __nv_bfloat16 l1 = __float2bfloat16(v.y - __bfloat162float(h1));
    __nv_bfloat16 l2 = __float2bfloat16(v.z - __bfloat162float(h2));
    __nv_bfloat16 l3 = __float2bfloat16(v.w - __bfloat162float(h3));
    uint2 hp, lp;
    hp.x = (uint32_t)__bfloat16_as_ushort(h0) | ((uint32_t)__bfloat16_as_ushort(h1) << 16);
    hp.y = (uint32_t)__bfloat16_as_ushort(h2) | ((uint32_t)__bfloat16_as_ushort(h3) << 16);
    lp.x = (uint32_t)__bfloat16_as_ushort(l0) | ((uint32_t)__bfloat16_as_ushort(l1) << 16);
    lp.y = (uint32_t)__bfloat16_as_ushort(l2) | ((uint32_t)__bfloat16_as_ushort(l3) << 16);
    *(uint2*)(smem + hi_off + row * RSTRIDE + lane * 8) = hp;
    *(uint2*)(smem + lo_off + row * RSTRIDE + lane * 8) = lp;
}

// ---------------- Kernel A: scores = Q K^T (bf16 3-term split) -> scratch ----------------
#define NT_A 512
#define AQHI 0
#define AQLO 34816
#define AKB(b) (69632 + (b) * 69632)
#define SMEM_A (69632 * 3)                    // 208896

__global__ __launch_bounds__(NT_A, 1)
void scores_kernel(const float* __restrict__ Qg, const float* __restrict__ Kg, int bh_base) {
    extern __shared__ char smem[];
    const uint32_t sb = smem_u32(smem);
    const int tid = threadIdx.x, wid = tid >> 5, lane = tid & 31;
    const int bh = bh_base + blockIdx.y, q0 = blockIdx.x * QPB;
    const float* Kb = Kg + (size_t)bh * S_LEN * D_DIM;

    {
        const float4* src = (const float4*)(Qg + ((size_t)bh * S_LEN + q0) * D_DIM);
        #pragma unroll
        for (int p = 0; p < 8; p++) {
            const int row = p * 16 + wid;
            cvt_store(smem, AQHI, AQLO, row, lane, __ldg(src + (size_t)row * 32 + lane));
        }
    }
    {
        #pragma unroll
        for (int p = 0; p < 8; p++) {
            const int row = p * 16 + wid;
            cvt_store(smem, AKB(0), AKB(0) + 34816, row, lane,
                      __ldg((const float4*)Kb + (size_t)row * 32 + lane));
        }
    }
    __syncthreads();

    const int wr = wid & 7, wc = wid >> 3;
    const uint32_t a_off = (uint32_t)((16 * wr + (((lane >> 3) & 1) << 3) + (lane & 7)) * RSTRIDE
                                      + ((lane >> 4) << 4));
    const uint32_t b_off = (uint32_t)((64 * wc + (((lane >> 4) & 1) << 3) + (lane & 7)) * RSTRIDE
                                      + (((lane >> 3) & 1) << 4));
    const int r0 = q0 + 16 * wr + (lane >> 2);
    float* srow0 = g_scores + ((size_t)(bh * S_LEN + r0)) * S_LEN;

    for (int kt = 0; kt < NKT; kt++) {
        float4 pf[8];
        if (kt < NKT - 1) {
            const float4* src = (const float4*)(Kb + (size_t)(kt + 1) * 128 * D_DIM);
            #pragma unroll
            for (int p = 0; p < 8; p++) pf[p] = __ldg(src + (size_t)(p * 16 + wid) * 32 + lane);
        }

        const uint32_t khi = sb + AKB(kt & 1), klo = khi + 34816;
        float acc[8][4];
        #pragma unroll
        for (int n = 0; n < 8; n++)
            #pragma unroll
            for (int r = 0; r < 4; r++) acc[n][r] = 0.f;

        #pragma unroll
        for (int ks = 0; ks < 8; ks++) {
            uint32_t ah[4], al[4];
            ldsm4(ah[0], ah[1], ah[2], ah[3], sb + AQHI + a_off + ks * 32);
            ldsm4(al[0], al[1], al[2], al[3], sb + AQLO + a_off + ks * 32);
            #pragma unroll
            for (int p = 0; p < 4; p++) {
                const uint32_t bo = b_off + (uint32_t)(p * 16 * RSTRIDE + ks * 32);
                uint32_t b0, b1, b2, b3, c0, c1, c2, c3;
                ldsm4(b0, b1, b2, b3, khi + bo);
                ldsm4(c0, c1, c2, c3, klo + bo);
                mma16816(acc[2 * p],     ah, b0, b1);
                mma16816(acc[2 * p + 1], ah, b2, b3);
                mma16816(acc[2 * p],     al, b0, b1);
                mma16816(acc[2 * p + 1], al, b2, b3);
                mma16816(acc[2 * p],     ah, c0, c1);
                mma16816(acc[2 * p + 1], ah, c2, c3);
            }
        }

        const int cb = kt * 128 + 64 * wc + 2 * (lane & 3);
        #pragma unroll
        for (int n = 0; n < 8; n++) {
            *(float2*)(srow0 + cb + 8 * n) = make_float2(acc[n][0], acc[n][1]);
            *(float2*)(srow0 + (size_t)8 * S_LEN + cb + 8 * n) = make_float2(acc[n][2], acc[n][3]);
        }

        if (kt < NKT - 1) {
            const uint32_t dst = AKB((kt + 1) & 1);
            #pragma unroll
            for (int p = 0; p < 8; p++)
                cvt_store(smem, dst, dst + 34816, p * 16 + wid, lane, pf[p]);
        }
        __syncthreads();
    }
}

// ---------------- Kernel B: warp-per-query top-32 via redux tournament ----------------
// 64-thread blocks + 16KB smem so select blocks co-reside with a scores CTA
// (smem 209+16 <= 228 KB, regs 512*~110 + 64*~72 <= 64K) and fill its wave gaps.
#define NT_B 64
#define BWARPS 2
#define SMEM_B (BWARPS * 32 * 64 * 4)   // 16384

__device__ __forceinline__ unsigned fmono(float f) {
    unsigned u = __float_as_uint(f);
    return u ^ ((unsigned)((int)u >> 31) | 0x80000000u);
}
__device__ __forceinline__ float funmono(unsigned m) {
    return __uint_as_float(m ^ ((unsigned)((int)(~m) >> 31) | 0x80000000u));
}

__global__ __launch_bounds__(NT_B, 6)
void select_kernel(const float* __restrict__ Vg, float* __restrict__ Og, int qbase) {
    extern __shared__ float sbuf[];
    const int tid = threadIdx.x, wid = tid >> 5, lane = tid & 31;
    const int q = qbase + blockIdx.x * BWARPS + wid;   // global query = bh*2048 + s
    const int bh = q >> 11;
    float* buf = sbuf + (size_t)wid * 2048;
    const float* srow = g_scores + (size_t)q * S_LEN;
    const unsigned FULL = 0xffffffffu;
    const int lsw = lane & 15;

    float bv = -FLT_MAX; int bj = 0;
    #pragma unroll
    for (int i = 0; i < 16; i++) {
        float4 v = __ldg((const float4*)srow + i * 32 + lane);
        ((float4*)buf)[lane * 16 + (i ^ lsw)] = v;
        if (v.x > bv) { bv = v.x; bj = 4 * i; }
        if (v.y > bv) { bv = v.y; bj = 4 * i + 1; }
        if (v.z > bv) { bv = v.z; bj = 4 * i + 2; }
        if (v.w > bv) { bv = v.w; bj = 4 * i + 3; }
    }
    __syncwarp();

    float    selval = 0.f;
    unsigned selkey = 0;
    #pragma unroll 1
    for (int r = 0; r < KTOP; r++) {
        const unsigned mym = fmono(bv);
        const unsigned wm  = __reduce_max_sync(FULL, mym);
        const unsigned bal = __ballot_sync(FULL, mym == wm);
        const int wl = __ffs(bal) - 1;
        const int bjw = __shfl_sync(FULL, bj, wl);
        if (lane == r) {
            selval = funmono(wm);
            selkey = ((unsigned)(bjw >> 2) << 7) | ((unsigned)wl << 2) | (unsigned)(bjw & 3);
        }

        if (lane == wl)
            buf[lane * 64 + (((bj >> 2) ^ lsw) << 2) + (bj & 3)] = -FLT_MAX;
        __syncwarp();

        const int wsw = wl & 15;
        const float2 vv = *(const float2*)(buf + wl * 64 + (((lane >> 1) ^ wsw) << 2) + ((lane & 1) << 1));
        float rv; int rj;
        if (vv.x >= vv.y) { rv = vv.x; rj = 2 * lane; } else { rv = vv.y; rj = 2 * lane + 1; }
        const unsigned rm = fmono(rv);
        const unsigned rw = __reduce_max_sync(FULL, rm);
        const unsigned rb = __ballot_sync(FULL, rm == rw);
        const int rjw = __shfl_sync(FULL, rj, __ffs(rb) - 1);
        if (lane == wl) { bv = funmono(rw); bj = rjw; }
        __syncwarp();
    }

    const float mx = __shfl_sync(FULL, selval, 0);
    const float e = __expf(selval - mx);
    float s = e;
    #pragma unroll
    for (int o = 16; o; o >>= 1) s += __shfl_xor_sync(FULL, s, o);
    const float p = e / s;

    const float* Vb = Vg + (size_t)bh * S_LEN * D_DIM;
    float4 a = make_float4(0.f, 0.f, 0.f, 0.f);
    #pragma unroll 4
    for (int j = 0; j < KTOP; j++) {
        const float    pj = __shfl_sync(FULL, p, j);
        const unsigned kj = __shfl_sync(FULL, selkey, j);
        float4 v = __ldg((const float4*)(Vb + (size_t)kj * D_DIM) + lane);
        a.x += pj * v.x; a.y += pj * v.y; a.z += pj * v.z; a.w += pj * v.w;
    }
    ((float4*)(Og + (size_t)q * D_DIM))[lane] = a;
}

// ---------------- Launcher: fork-join two-stream pipeline over bh chunks ----------------
#define NCHUNK 4

extern "C" void kernel_launch(void* const* d_in, const int* in_sizes, int n_in,
                              void* d_out, int out_size) {
    const float* Q = (const float*)d_in[0];
    const float* K = (const float*)d_in[1];
    const float* V = (const float*)d_in[2];
    float* O = (float*)d_out;
    const int BH = in_sizes[0] / (S_LEN * D_DIM);   // 32

    static bool init_done = false;
    static cudaStream_t s2;
    static cudaEvent_t evA[NCHUNK], evJoin;
    if (!init_done) {   // first call is the uncaptured correctness run
        cudaStreamCreateWithFlags(&s2, cudaStreamNonBlocking);
        for (int c = 0; c < NCHUNK; c++) cudaEventCreateWithFlags(&evA[c], cudaEventDisableTiming);
        cudaEventCreateWithFlags(&evJoin, cudaEventDisableTiming);
        cudaFuncSetAttribute(scores_kernel, cudaFuncAttributeMaxDynamicSharedMemorySize, SMEM_A);
        cudaFuncSetAttribute(select_kernel, cudaFuncAttributeMaxDynamicSharedMemorySize, SMEM_B);
        init_done = true;
    }

    // capture-origin stream: the harness calls us on its stream via the default
    // stream semantics of <<<>>>; use stream 0 (legacy default participates in capture).
    cudaStream_t s1 = 0;

    if (BH % NCHUNK == 0) {
        const int bhpc = BH / NCHUNK;                  // 8
        const int qpc  = bhpc * S_LEN;                 // 16384 queries per chunk
        for (int c = 0; c < NCHUNK; c++) {
            dim3 gA(S_LEN / QPB, bhpc);
            scores_kernel<<<gA, NT_A, SMEM_A, s1>>>(Q, K, c * bhpc);
            cudaEventRecord(evA[c], s1);
            cudaStreamWaitEvent(s2, evA[c], 0);
            select_kernel<<<qpc / BWARPS, NT_B, SMEM_B, s2>>>(V, O, c * qpc);
        }
        cudaEventRecord(evJoin, s2);
        cudaStreamWaitEvent(s1, evJoin, 0);
    } else {
        // fallback: sequential single-stream path
        dim3 gA(S_LEN / QPB, BH);
        scores_kernel<<<gA, NT_A, SMEM_A, s1>>>(Q, K, 0);
        select_kernel<<<BH * S_LEN / BWARPS, NT_B, SMEM_B, s1>>>(V, O, 0);
    }
}

// round 7
// speedup vs baseline: 1.0462x; 1.0462x over previous
#include <cuda_runtime.h>
#include <cuda_bf16.h>
#include <cstdint>
#include <cfloat>

#define S_LEN 2048
#define D_DIM 128
#define QPB   128
#define KTOP  32
#define RSTRIDE 272        // bf16 tile row stride (17*16B): conflict-free ldmatrix
#define KROWS 64           // keys per K tile
#define NKT2  (S_LEN / KROWS)   // 32 tiles

// 512 MB global scratch for the full score matrix [BH=32][2048][2048] fp32
__device__ float g_scores[(size_t)32 * S_LEN * S_LEN];

__device__ __forceinline__ uint32_t smem_u32(const void* p) {
    uint32_t a;
    asm("{ .reg .u64 t; cvta.to.shared.u64 t, %1; cvt.u32.u64 %0, t; }" : "=r"(a) : "l"(p));
    return a;
}

__device__ __forceinline__ void ldsm4(uint32_t& r0, uint32_t& r1, uint32_t& r2, uint32_t& r3,
                                      uint32_t addr) {
    asm volatile("ldmatrix.sync.aligned.m8n8.x4.shared.b16 {%0,%1,%2,%3}, [%4];"
                 : "=r"(r0), "=r"(r1), "=r"(r2), "=r"(r3) : "r"(addr));
}

__device__ __forceinline__ void mma16816(float* c, const uint32_t* a, uint32_t b0, uint32_t b1) {
    asm volatile(
        "mma.sync.aligned.m16n8k16.row.col.f32.bf16.bf16.f32 "
        "{%0,%1,%2,%3}, {%4,%5,%6,%7}, {%8,%9}, {%0,%1,%2,%3};"
        : "+f"(c[0]), "+f"(c[1]), "+f"(c[2]), "+f"(c[3])
        : "r"(a[0]), "r"(a[1]), "r"(a[2]), "r"(a[3]), "r"(b0), "r"(b1));
}

__device__ __forceinline__ void cvt_store(char* smem, uint32_t hi_off, uint32_t lo_off,
                                          int row, int lane, float4 v) {
    __nv_bfloat16 h0 = __float2bfloat16(v.x), h1 = __float2bfloat16(v.y);
    __nv_bfloat16 h2 = __float2bfloat16(v.z), h3 = __float2bfloat16(v.w);
    __nv_bfloat16 l0 = __float2bfloat16(v.x - __bfloat162float(h0));
    __nv_bfloat16 l1 = __float2bfloat16(v.y - __bfloat162float(h1));
    __nv_bfloat16 l2 = __float2bfloat16(v.z - __bfloat162float(h2));
    __nv_bfloat16 l3 = __float2bfloat16(v.w - __bfloat162float(h3));
    uint2 hp, lp;
    hp.x = (uint32_t)__bfloat16_as_ushort(h0) | ((uint32_t)__bfloat16_as_ushort(h1) << 16);
    hp.y = (uint32_t)__bfloat16_as_ushort(h2) | ((uint32_t)__bfloat16_as_ushort(h3) << 16);
    lp.x = (uint32_t)__bfloat16_as_ushort(l0) | ((uint32_t)__bfloat16_as_ushort(l1) << 16);
    lp.y = (uint32_t)__bfloat16_as_ushort(l2) | ((uint32_t)__bfloat16_as_ushort(l3) << 16);
    *(uint2*)(smem + hi_off + row * RSTRIDE + lane * 8) = hp;
    *(uint2*)(smem + lo_off + row * RSTRIDE + lane * 8) = lp;
}

// ---------------- Kernel A: scores = Q K^T (bf16 3-term split) -> scratch ----------------
// 256 threads / 139 KB smem / ~120 regs: leaves ~89 KB smem + ~33K regs per SM
// so select blocks co-reside and consume the ~80% idle issue slots.
#define NT_A 256
#define AQHI 0
#define AQLO 34816
#define AKHI(b) (69632 + (b) * 34816)          // K buf b: hi, lo at +17408
#define SMEM_A 139264

__global__ __launch_bounds__(NT_A, 1)
void scores_kernel(const float* __restrict__ Qg, const float* __restrict__ Kg, int bh_base) {
    extern __shared__ char smem[];
    const uint32_t sb = smem_u32(smem);
    const int tid = threadIdx.x, wid = tid >> 5, lane = tid & 31;
    const int bh = bh_base + blockIdx.y, q0 = blockIdx.x * QPB;
    const float* Kb = Kg + (size_t)bh * S_LEN * D_DIM;

    // Split Q (128x128): 16 passes, row = p*8 + wid.
    {
        const float4* src = (const float4*)(Qg + ((size_t)bh * S_LEN + q0) * D_DIM);
        #pragma unroll
        for (int p = 0; p < 16; p++) {
            const int row = p * 8 + wid;
            cvt_store(smem, AQHI, AQLO, row, lane, __ldg(src + (size_t)row * 32 + lane));
        }
    }
    // Split K tile 0 (64x128) into buffer 0.
    {
        #pragma unroll
        for (int p = 0; p < 8; p++) {
            const int row = p * 8 + wid;
            cvt_store(smem, AKHI(0), AKHI(0) + 17408, row, lane,
                      __ldg((const float4*)Kb + (size_t)row * 32 + lane));
        }
    }
    __syncthreads();

    // warp wid owns M strip [16*wid, 16*wid+16) x all 64 keys of the tile
    const uint32_t a_off = (uint32_t)((16 * wid + (((lane >> 3) & 1) << 3) + (lane & 7)) * RSTRIDE
                                      + ((lane >> 4) << 4));
    const uint32_t b_off = (uint32_t)(((((lane >> 4) & 1) << 3) + (lane & 7)) * RSTRIDE
                                      + (((lane >> 3) & 1) << 4));
    const int r0 = q0 + 16 * wid + (lane >> 2);
    float* srow0 = g_scores + ((size_t)(bh * S_LEN + r0)) * S_LEN;

    for (int kt = 0; kt < NKT2; kt++) {
        // register-prefetch next 64-key tile (hidden behind MMAs)
        float4 pf[8];
        if (kt < NKT2 - 1) {
            const float4* src = (const float4*)(Kb + (size_t)(kt + 1) * KROWS * D_DIM);
            #pragma unroll
            for (int p = 0; p < 8; p++) pf[p] = __ldg(src + (size_t)(p * 8 + wid) * 32 + lane);
        }

        const uint32_t khi = sb + AKHI(kt & 1), klo = khi + 17408;
        float acc[8][4];
        #pragma unroll
        for (int n = 0; n < 8; n++)
            #pragma unroll
            for (int r = 0; r < 4; r++) acc[n][r] = 0.f;

        #pragma unroll
        for (int ks = 0; ks < 8; ks++) {
            uint32_t ah[4], al[4];
            ldsm4(ah[0], ah[1], ah[2], ah[3], sb + AQHI + a_off + ks * 32);
            ldsm4(al[0], al[1], al[2], al[3], sb + AQLO + a_off + ks * 32);
            #pragma unroll
            for (int p = 0; p < 4; p++) {
                const uint32_t bo = b_off + (uint32_t)(p * 16 * RSTRIDE + ks * 32);
                uint32_t b0, b1, b2, b3, c0, c1, c2, c3;
                ldsm4(b0, b1, b2, b3, khi + bo);
                ldsm4(c0, c1, c2, c3, klo + bo);
                mma16816(acc[2 * p],     ah, b0, b1);
                mma16816(acc[2 * p + 1], ah, b2, b3);
                mma16816(acc[2 * p],     al, b0, b1);
                mma16816(acc[2 * p + 1], al, b2, b3);
                mma16816(acc[2 * p],     ah, c0, c1);
                mma16816(acc[2 * p + 1], ah, c2, c3);
            }
        }

        const int cb = kt * KROWS + 2 * (lane & 3);
        #pragma unroll
        for (int n = 0; n < 8; n++) {
            *(float2*)(srow0 + cb + 8 * n) = make_float2(acc[n][0], acc[n][1]);
            *(float2*)(srow0 + (size_t)8 * S_LEN + cb + 8 * n) = make_float2(acc[n][2], acc[n][3]);
        }

        if (kt < NKT2 - 1) {
            const uint32_t dhi = AKHI((kt + 1) & 1);
            #pragma unroll
            for (int p = 0; p < 8; p++)
                cvt_store(smem, dhi, dhi + 17408, p * 8 + wid, lane, pf[p]);
        }
        __syncthreads();
    }
}

// ---------------- Kernel B: warp-per-query top-32 via redux tournament ----------------
#define NT_B 64
#define BWARPS 2
#define SMEM_B (BWARPS * 32 * 64 * 4)   // 16384

__device__ __forceinline__ unsigned fmono(float f) {
    unsigned u = __float_as_uint(f);
    return u ^ ((unsigned)((int)u >> 31) | 0x80000000u);
}
__device__ __forceinline__ float funmono(unsigned m) {
    return __uint_as_float(m ^ ((unsigned)((int)(~m) >> 31) | 0x80000000u));
}

__global__ __launch_bounds__(NT_B, 8)
void select_kernel(const float* __restrict__ Vg, float* __restrict__ Og, int qbase) {
    extern __shared__ float sbuf[];
    const int tid = threadIdx.x, wid = tid >> 5, lane = tid & 31;
    const int q = qbase + blockIdx.x * BWARPS + wid;
    const int bh = q >> 11;
    float* buf = sbuf + (size_t)wid * 2048;
    const float* srow = g_scores + (size_t)q * S_LEN;
    const unsigned FULL = 0xffffffffu;
    const int lsw = lane & 15;

    float bv = -FLT_MAX; int bj = 0;
    #pragma unroll
    for (int i = 0; i < 16; i++) {
        float4 v = __ldg((const float4*)srow + i * 32 + lane);
        ((float4*)buf)[lane * 16 + (i ^ lsw)] = v;
        if (v.x > bv) { bv = v.x; bj = 4 * i; }
        if (v.y > bv) { bv = v.y; bj = 4 * i + 1; }
        if (v.z > bv) { bv = v.z; bj = 4 * i + 2; }
        if (v.w > bv) { bv = v.w; bj = 4 * i + 3; }
    }
    __syncwarp();

    float    selval = 0.f;
    unsigned selkey = 0;
    #pragma unroll 1
    for (int r = 0; r < KTOP; r++) {
        const unsigned mym = fmono(bv);
        const unsigned wm  = __reduce_max_sync(FULL, mym);
        const unsigned bal = __ballot_sync(FULL, mym == wm);
        const int wl = __ffs(bal) - 1;
        const int bjw = __shfl_sync(FULL, bj, wl);
        if (lane == r) {
            selval = funmono(wm);
            selkey = ((unsigned)(bjw >> 2) << 7) | ((unsigned)wl << 2) | (unsigned)(bjw & 3);
        }

        if (lane == wl)
            buf[lane * 64 + (((bj >> 2) ^ lsw) << 2) + (bj & 3)] = -FLT_MAX;
        __syncwarp();

        const int wsw = wl & 15;
        const float2 vv = *(const float2*)(buf + wl * 64 + (((lane >> 1) ^ wsw) << 2) + ((lane & 1) << 1));
        float rv; int rj;
        if (vv.x >= vv.y) { rv = vv.x; rj = 2 * lane; } else { rv = vv.y; rj = 2 * lane + 1; }
        const unsigned rm = fmono(rv);
        const unsigned rw = __reduce_max_sync(FULL, rm);
        const unsigned rb = __ballot_sync(FULL, rm == rw);
        const int rjw = __shfl_sync(FULL, rj, __ffs(rb) - 1);
        if (lane == wl) { bv = funmono(rw); bj = rjw; }
        __syncwarp();
    }

    const float mx = __shfl_sync(FULL, selval, 0);
    const float e = __expf(selval - mx);
    float s = e;
    #pragma unroll
    for (int o = 16; o; o >>= 1) s += __shfl_xor_sync(FULL, s, o);
    const float p = e / s;

    const float* Vb = Vg + (size_t)bh * S_LEN * D_DIM;
    float4 a = make_float4(0.f, 0.f, 0.f, 0.f);
    #pragma unroll 4
    for (int j = 0; j < KTOP; j++) {
        const float    pj = __shfl_sync(FULL, p, j);
        const unsigned kj = __shfl_sync(FULL, selkey, j);
        float4 v = __ldg((const float4*)(Vb + (size_t)kj * D_DIM) + lane);
        a.x += pj * v.x; a.y += pj * v.y; a.z += pj * v.z; a.w += pj * v.w;
    }
    ((float4*)(Og + (size_t)q * D_DIM))[lane] = a;
}

// ---------------- Launcher: scores chunks alternate on 2 streams (no wave
// quantization); select chunks on a 3rd stream gated by per-chunk events. ----
#define NCHUNK 4

extern "C" void kernel_launch(void* const* d_in, const int* in_sizes, int n_in,
                              void* d_out, int out_size) {
    const float* Q = (const float*)d_in[0];
    const float* K = (const float*)d_in[1];
    const float* V = (const float*)d_in[2];
    float* O = (float*)d_out;
    const int BH = in_sizes[0] / (S_LEN * D_DIM);   // 32

    static bool init_done = false;
    static cudaStream_t sA, sB, sC;
    static cudaEvent_t evRoot, evS[NCHUNK], evEA, evEB, evEC;
    if (!init_done) {   // first call is the uncaptured correctness run
        cudaStreamCreateWithFlags(&sA, cudaStreamNonBlocking);
        cudaStreamCreateWithFlags(&sB, cudaStreamNonBlocking);
        cudaStreamCreateWithFlags(&sC, cudaStreamNonBlocking);
        cudaEventCreateWithFlags(&evRoot, cudaEventDisableTiming);
        for (int c = 0; c < NCHUNK; c++) cudaEventCreateWithFlags(&evS[c], cudaEventDisableTiming);
        cudaEventCreateWithFlags(&evEA, cudaEventDisableTiming);
        cudaEventCreateWithFlags(&evEB, cudaEventDisableTiming);
        cudaEventCreateWithFlags(&evEC, cudaEventDisableTiming);
        cudaFuncSetAttribute(scores_kernel, cudaFuncAttributeMaxDynamicSharedMemorySize, SMEM_A);
        cudaFuncSetAttribute(select_kernel, cudaFuncAttributeMaxDynamicSharedMemorySize, SMEM_B);
        init_done = true;
    }

    if (BH % NCHUNK == 0) {
        const int bhpc = BH / NCHUNK;                  // 8
        const int qpc  = bhpc * S_LEN;                 // 16384
        cudaEventRecord(evRoot, 0);
        cudaStreamWaitEvent(sA, evRoot, 0);
        cudaStreamWaitEvent(sB, evRoot, 0);
        for (int c = 0; c < NCHUNK; c++) {
            cudaStream_t ss = (c & 1) ? sB : sA;
            dim3 gA(S_LEN / QPB, bhpc);
            scores_kernel<<<gA, NT_A, SMEM_A, ss>>>(Q, K, c * bhpc);
            cudaEventRecord(evS[c], ss);
            cudaStreamWaitEvent(sC, evS[c], 0);
            select_kernel<<<qpc / BWARPS, NT_B, SMEM_B, sC>>>(V, O, c * qpc);
        }
        cudaEventRecord(evEA, sA);
        cudaEventRecord(evEB, sB);
        cudaEventRecord(evEC, sC);
        cudaStreamWaitEvent(0, evEA, 0);
        cudaStreamWaitEvent(0, evEB, 0);
        cudaStreamWaitEvent(0, evEC, 0);
    } else {
        dim3 gA(S_LEN / QPB, BH);
        scores_kernel<<<gA, NT_A, SMEM_A, 0>>>(Q, K, 0);
        select_kernel<<<BH * S_LEN / BWARPS, NT_B, SMEM_B, 0>>>(V, O, 0);
    }
}